// round 3
// baseline (speedup 1.0000x reference)
#include <cuda_runtime.h>

#define Tt 2048
#define Dd 1024
#define Ff 4096
#define Ee 8
#define NROWS (Tt * 2)   // T * TOPK

typedef unsigned long long u64;

// Scratch (device globals: allocation-free, graph-safe)
__device__ float g_fuse[(size_t)NROWS * Ff];   // 64 MB, compacted by expert bucket
__device__ float g_down[(size_t)NROWS * Dd];   // 16 MB, indexed by rid = t*2+k
__device__ int   g_bucket[NROWS];              // rid list grouped by expert
__device__ int   g_offs[Ee + 1];
__device__ float g_topw[NROWS];
__device__ int   g_topidx[NROWS];

// ---------- packed fp32x2 helpers (FFMA2 path: 2x FFMA throughput) ----------
__device__ __forceinline__ u64 pack2(float v) {
    unsigned u = __float_as_uint(v);
    u64 r;
    asm("mov.b64 %0, {%1, %2};" : "=l"(r) : "r"(u), "r"(u));
    return r;
}
__device__ __forceinline__ void unpack2(u64 v, float& lo, float& hi) {
    unsigned a, b;
    asm("mov.b64 {%0, %1}, %2;" : "=r"(a), "=r"(b) : "l"(v));
    lo = __uint_as_float(a);
    hi = __uint_as_float(b);
}
__device__ __forceinline__ void fma2(u64& d, u64 a, u64 b) {
    asm("fma.rn.f32x2 %0, %1, %2, %0;" : "+l"(d) : "l"(a), "l"(b));
}
__device__ __forceinline__ float silu(float g) {
    return g / (1.f + __expf(-g));
}

// ---------------------- 1. Router: logits + top2 + softmax ----------------------
__global__ void router_kernel(const float* __restrict__ x, const float* __restrict__ rw) {
    int gw   = (blockIdx.x * blockDim.x + threadIdx.x) >> 5;
    int lane = threadIdx.x & 31;
    if (gw >= Tt) return;
    const float* xr = x + (size_t)gw * Dd;
    float acc[Ee];
#pragma unroll
    for (int e = 0; e < Ee; e++) acc[e] = 0.f;
    for (int d = lane; d < Dd; d += 32) {
        float xv = xr[d];
        const float4* r = (const float4*)(rw + (size_t)d * Ee);
        float4 r0 = r[0], r1 = r[1];
        acc[0] += xv * r0.x; acc[1] += xv * r0.y;
        acc[2] += xv * r0.z; acc[3] += xv * r0.w;
        acc[4] += xv * r1.x; acc[5] += xv * r1.y;
        acc[6] += xv * r1.z; acc[7] += xv * r1.w;
    }
#pragma unroll
    for (int e = 0; e < Ee; e++) {
#pragma unroll
        for (int off = 16; off > 0; off >>= 1)
            acc[e] += __shfl_xor_sync(0xffffffffu, acc[e], off);
    }
    if (lane == 0) {
        int i0 = 0;
#pragma unroll
        for (int e = 1; e < Ee; e++) if (acc[e] > acc[i0]) i0 = e;
        int i1 = (i0 == 0) ? 1 : 0;
#pragma unroll
        for (int e = 0; e < Ee; e++) if (e != i0 && acc[e] > acc[i1]) i1 = e;
        float ex = __expf(acc[i1] - acc[i0]);   // second <= first
        float w0 = 1.f / (1.f + ex);
        float w1 = ex * w0;
        g_topidx[gw * 2 + 0] = i0;
        g_topidx[gw * 2 + 1] = i1;
        g_topw[gw * 2 + 0] = w0;
        g_topw[gw * 2 + 1] = w1;
    }
}

// ---------------------- 2. Bucket compaction (single block) ----------------------
__global__ void compact_kernel() {
    __shared__ int s_cnt[Ee], s_cur[Ee], s_off[Ee + 1];
    int tid = threadIdx.x;
    if (tid < Ee) { s_cnt[tid] = 0; s_cur[tid] = 0; }
    __syncthreads();
    for (int r = tid; r < NROWS; r += blockDim.x)
        atomicAdd(&s_cnt[g_topidx[r]], 1);
    __syncthreads();
    if (tid == 0) {
        int acc = 0;
        for (int e = 0; e < Ee; e++) { s_off[e] = acc; acc += s_cnt[e]; }
        s_off[Ee] = acc;
        for (int e = 0; e <= Ee; e++) g_offs[e] = s_off[e];
    }
    __syncthreads();
    for (int r = tid; r < NROWS; r += blockDim.x) {
        int e = g_topidx[r];
        int p = atomicAdd(&s_cur[e], 1);
        g_bucket[s_off[e] + p] = r;
    }
}

// ---------------------- 3. GEMM1: gathered X @ (Wg, Wu), fused SiLU ----------------------
// Block: 128(M) x 64(N) x 16(K), 256 threads, thread tile 8x4 per matrix (f32x2-packed rows)
__global__ void __launch_bounds__(256) gemm1_kernel(
    const float* __restrict__ x,
    const float* __restrict__ wg,
    const float* __restrict__ wu)
{
    const int e   = blockIdx.z;
    const int off = g_offs[e];
    const int n_e = g_offs[e + 1] - off;
    const int m0  = blockIdx.y * 128;
    if (m0 >= n_e) return;
    const int n0  = blockIdx.x * 64;

    __shared__ float As[2][16][128];
    __shared__ float Bg[2][16][64];
    __shared__ float Bu[2][16][64];

    const int tid   = threadIdx.x;
    const int arow0 = tid >> 2;          // 0..63
    const int arow1 = arow0 + 64;
    const int ak    = (tid & 3) << 2;    // 0,4,8,12
    const int brow  = tid >> 4;          // 0..15
    const int bcol  = (tid & 15) << 2;   // 0..60

    // Gathered A rows (clamped: out-of-range rows duplicate the last valid row,
    // their results are discarded in the epilogue)
    const int tok0 = g_bucket[off + min(m0 + arow0, n_e - 1)] >> 1;
    const int tok1 = g_bucket[off + min(m0 + arow1, n_e - 1)] >> 1;
    const float* xa0 = x + (size_t)tok0 * Dd + ak;
    const float* xa1 = x + (size_t)tok1 * Dd + ak;
    const float* wge = wg + (size_t)e * Dd * Ff + (size_t)brow * Ff + n0 + bcol;
    const float* wue = wu + (size_t)e * Dd * Ff + (size_t)brow * Ff + n0 + bcol;

    float4 ra0 = *(const float4*)xa0;
    float4 ra1 = *(const float4*)xa1;
    float4 rbg = *(const float4*)wge;
    float4 rbu = *(const float4*)wue;

    u64 cg[4][4], cu[4][4];
#pragma unroll
    for (int i = 0; i < 4; i++)
#pragma unroll
        for (int j = 0; j < 4; j++) { cg[i][j] = 0ull; cu[i][j] = 0ull; }

    const int ty = tid >> 4, tx = tid & 15;
    const int rbase = ty * 8, cbase = tx * 4;

    const int NIT = Dd / 16;   // 64
    for (int it = 0; it < NIT; ++it) {
        const int s = it & 1;
        As[s][ak + 0][arow0] = ra0.x; As[s][ak + 1][arow0] = ra0.y;
        As[s][ak + 2][arow0] = ra0.z; As[s][ak + 3][arow0] = ra0.w;
        As[s][ak + 0][arow1] = ra1.x; As[s][ak + 1][arow1] = ra1.y;
        As[s][ak + 2][arow1] = ra1.z; As[s][ak + 3][arow1] = ra1.w;
        *(float4*)&Bg[s][brow][bcol] = rbg;
        *(float4*)&Bu[s][brow][bcol] = rbu;
        __syncthreads();

        if (it + 1 < NIT) {
            const int k0 = (it + 1) * 16;
            ra0 = *(const float4*)(xa0 + k0);
            ra1 = *(const float4*)(xa1 + k0);
            rbg = *(const float4*)(wge + (size_t)k0 * Ff);
            rbu = *(const float4*)(wue + (size_t)k0 * Ff);
        }

#pragma unroll
        for (int kk = 0; kk < 16; ++kk) {
            const u64* ap = (const u64*)&As[s][kk][rbase];
            u64 a[4];
            a[0] = ap[0]; a[1] = ap[1]; a[2] = ap[2]; a[3] = ap[3];
            float4 bg4 = *(const float4*)&Bg[s][kk][cbase];
            float4 bu4 = *(const float4*)&Bu[s][kk][cbase];
            float gs[4] = {bg4.x, bg4.y, bg4.z, bg4.w};
            float us[4] = {bu4.x, bu4.y, bu4.z, bu4.w};
#pragma unroll
            for (int j = 0; j < 4; j++) {
                u64 b = pack2(gs[j]);
#pragma unroll
                for (int i = 0; i < 4; i++) fma2(cg[i][j], a[i], b);
            }
#pragma unroll
            for (int j = 0; j < 4; j++) {
                u64 b = pack2(us[j]);
#pragma unroll
                for (int i = 0; i < 4; i++) fma2(cu[i][j], a[i], b);
            }
        }
    }

    // Epilogue: fuse = silu(gate) * up  -> compacted g_fuse rows
#pragma unroll
    for (int i2 = 0; i2 < 4; i2++) {
        float glo[4], ghi[4], ulo[4], uhi[4];
#pragma unroll
        for (int j = 0; j < 4; j++) {
            unpack2(cg[i2][j], glo[j], ghi[j]);
            unpack2(cu[i2][j], ulo[j], uhi[j]);
        }
        int r = m0 + rbase + 2 * i2;
        if (r < n_e) {
            float4 v;
            v.x = silu(glo[0]) * ulo[0];
            v.y = silu(glo[1]) * ulo[1];
            v.z = silu(glo[2]) * ulo[2];
            v.w = silu(glo[3]) * ulo[3];
            *(float4*)&g_fuse[(size_t)(off + r) * Ff + n0 + cbase] = v;
        }
        if (r + 1 < n_e) {
            float4 v;
            v.x = silu(ghi[0]) * uhi[0];
            v.y = silu(ghi[1]) * uhi[1];
            v.z = silu(ghi[2]) * uhi[2];
            v.w = silu(ghi[3]) * uhi[3];
            *(float4*)&g_fuse[(size_t)(off + r + 1) * Ff + n0 + cbase] = v;
        }
    }
}

// ---------------------- 4. GEMM2: fuse @ Wd -> g_down[rid] ----------------------
// Block: 128(M) x 128(N) x 16(K), 256 threads, thread tile 8x8
__global__ void __launch_bounds__(256) gemm2_kernel(const float* __restrict__ wd)
{
    const int e   = blockIdx.z;
    const int off = g_offs[e];
    const int n_e = g_offs[e + 1] - off;
    const int m0  = blockIdx.y * 128;
    if (m0 >= n_e) return;
    const int n0  = blockIdx.x * 128;

    __shared__ float As[2][16][128];
    __shared__ float Bs[2][16][128];

    const int tid   = threadIdx.x;
    const int arow0 = tid >> 2;
    const int arow1 = arow0 + 64;
    const int ak    = (tid & 3) << 2;
    const int brow0 = tid >> 5;            // 0..7
    const int brow1 = brow0 + 8;
    const int bcol  = (tid & 31) << 2;     // 0..124

    const int ar0 = off + min(m0 + arow0, n_e - 1);
    const int ar1 = off + min(m0 + arow1, n_e - 1);
    const float* fa0 = g_fuse + (size_t)ar0 * Ff + ak;
    const float* fa1 = g_fuse + (size_t)ar1 * Ff + ak;
    const float* wde = wd + (size_t)e * Ff * Dd + n0 + bcol;

    float4 ra0 = *(const float4*)fa0;
    float4 ra1 = *(const float4*)fa1;
    float4 rb0 = *(const float4*)(wde + (size_t)brow0 * Dd);
    float4 rb1 = *(const float4*)(wde + (size_t)brow1 * Dd);

    u64 c[4][8];
#pragma unroll
    for (int i = 0; i < 4; i++)
#pragma unroll
        for (int j = 0; j < 8; j++) c[i][j] = 0ull;

    const int ty = tid >> 4, tx = tid & 15;
    const int rbase = ty * 8, cbase = tx * 8;

    const int NIT = Ff / 16;   // 256
    for (int it = 0; it < NIT; ++it) {
        const int s = it & 1;
        As[s][ak + 0][arow0] = ra0.x; As[s][ak + 1][arow0] = ra0.y;
        As[s][ak + 2][arow0] = ra0.z; As[s][ak + 3][arow0] = ra0.w;
        As[s][ak + 0][arow1] = ra1.x; As[s][ak + 1][arow1] = ra1.y;
        As[s][ak + 2][arow1] = ra1.z; As[s][ak + 3][arow1] = ra1.w;
        *(float4*)&Bs[s][brow0][bcol] = rb0;
        *(float4*)&Bs[s][brow1][bcol] = rb1;
        __syncthreads();

        if (it + 1 < NIT) {
            const int k0 = (it + 1) * 16;
            ra0 = *(const float4*)(fa0 + k0);
            ra1 = *(const float4*)(fa1 + k0);
            rb0 = *(const float4*)(wde + (size_t)(k0 + brow0) * Dd);
            rb1 = *(const float4*)(wde + (size_t)(k0 + brow1) * Dd);
        }

#pragma unroll
        for (int kk = 0; kk < 16; ++kk) {
            const u64* ap = (const u64*)&As[s][kk][rbase];
            u64 a[4];
            a[0] = ap[0]; a[1] = ap[1]; a[2] = ap[2]; a[3] = ap[3];
            float4 b4a = *(const float4*)&Bs[s][kk][cbase];
            float4 b4b = *(const float4*)&Bs[s][kk][cbase + 4];
            float bs[8] = {b4a.x, b4a.y, b4a.z, b4a.w, b4b.x, b4b.y, b4b.z, b4b.w};
#pragma unroll
            for (int j = 0; j < 8; j++) {
                u64 b = pack2(bs[j]);
#pragma unroll
                for (int i = 0; i < 4; i++) fma2(c[i][j], a[i], b);
            }
        }
    }

    // Epilogue: scatter rows by rid (deterministic: each rid written once)
#pragma unroll
    for (int i2 = 0; i2 < 4; i2++) {
        int r = m0 + rbase + 2 * i2;
        float lo[8], hi[8];
#pragma unroll
        for (int j = 0; j < 8; j++) unpack2(c[i2][j], lo[j], hi[j]);
        if (r < n_e) {
            int rid = g_bucket[off + r];
            float* dst = g_down + (size_t)rid * Dd + n0 + cbase;
            *(float4*)dst       = make_float4(lo[0], lo[1], lo[2], lo[3]);
            *(float4*)(dst + 4) = make_float4(lo[4], lo[5], lo[6], lo[7]);
        }
        if (r + 1 < n_e) {
            int rid = g_bucket[off + r + 1];
            float* dst = g_down + (size_t)rid * Dd + n0 + cbase;
            *(float4*)dst       = make_float4(hi[0], hi[1], hi[2], hi[3]);
            *(float4*)(dst + 4) = make_float4(hi[4], hi[5], hi[6], hi[7]);
        }
    }
}

// ---------------------- 5. Weighted combine ----------------------
__global__ void combine_kernel(float* __restrict__ out) {
    int i = blockIdx.x * blockDim.x + threadIdx.x;
    const int n4 = Tt * Dd / 4;
    if (i >= n4) return;
    int t = i / (Dd / 4);
    int c = i % (Dd / 4);
    float w0 = g_topw[t * 2 + 0];
    float w1 = g_topw[t * 2 + 1];
    float4 a = ((const float4*)(g_down + (size_t)(t * 2 + 0) * Dd))[c];
    float4 b = ((const float4*)(g_down + (size_t)(t * 2 + 1) * Dd))[c];
    float4 r;
    r.x = w0 * a.x + w1 * b.x;
    r.y = w0 * a.y + w1 * b.y;
    r.z = w0 * a.z + w1 * b.z;
    r.w = w0 * a.w + w1 * b.w;
    ((float4*)out)[i] = r;
}

// ---------------------- launch ----------------------
extern "C" void kernel_launch(void* const* d_in, const int* in_sizes, int n_in,
                              void* d_out, int out_size) {
    const float* x  = (const float*)d_in[0];
    const float* rw = (const float*)d_in[1];
    const float* wg = (const float*)d_in[2];
    const float* wu = (const float*)d_in[3];
    const float* wd = (const float*)d_in[4];
    float* out = (float*)d_out;

    router_kernel<<<Tt / 8, 256>>>(x, rw);
    compact_kernel<<<1, 256>>>();

    dim3 g1(Ff / 64, (Tt + 127) / 128, Ee);
    gemm1_kernel<<<g1, 256>>>(x, wg, wu);

    dim3 g2(Dd / 128, (Tt + 127) / 128, Ee);
    gemm2_kernel<<<g2, 256>>>(wd);

    combine_kernel<<<(Tt * Dd / 4 + 255) / 256, 256>>>(out);
}